// round 1
// baseline (speedup 1.0000x reference)
#include <cuda_runtime.h>

typedef unsigned long long u64;

#define HH 224
#define WW 224
#define IMG (HH * WW)
#define NPASS 9
#define W3MASK 0xFFFFFFFFull

// bits 0..k-1 of word j (j*64 .. j*64+63) of a 224-bit mask
__device__ __forceinline__ u64 mask_lt(int k, int j) {
    int lo = j * 64;
    if (k <= lo) return 0ull;
    if (k >= lo + 64) return ~0ull;
    return (1ull << (k - lo)) - 1ull;
}

__global__ __launch_bounds__(128) void mask_ca_kernel(const float* __restrict__ x,
                                                      float* __restrict__ out) {
    __shared__ u64 s_mask[HH][4];
    __shared__ u64 s_b1[HH][4];
    __shared__ u64 s_b2[HH][4];
    __shared__ u64 s_n[HH][4];
    __shared__ u64 s_rect[4];
    __shared__ int s_hmin, s_hmax;

    const int tid  = threadIdx.x;
    const int lane = tid & 31;
    const int warp = tid >> 5;
    const float* xi = x + (size_t)blockIdx.x * IMG;
    float* oi = out + (size_t)blockIdx.x * IMG;

    // ---- pack input: threshold > 0.8 into 224-bit rows (4x u64) ----
    for (int r = warp; r < HH; r += 4) {
        const float* row = xi + r * WW;
        unsigned b[7];
#pragma unroll
        for (int c = 0; c < 7; c++)
            b[c] = __ballot_sync(0xFFFFFFFFu, row[c * 32 + lane] > 0.8f);
        if (lane == 0) {
            s_mask[r][0] = (u64)b[0] | ((u64)b[1] << 32);
            s_mask[r][1] = (u64)b[2] | ((u64)b[3] << 32);
            s_mask[r][2] = (u64)b[4] | ((u64)b[5] << 32);
            s_mask[r][3] = (u64)b[6];
        }
    }
    __syncthreads();

    for (int pass = 0; pass < NPASS; pass++) {
        // ---- parallel: base encoded as b1 (=exactly one of below/right), b2 (=both) ----
        for (int r = tid; r < HH; r += 128) {
            u64 g0 = s_mask[r][0], g1 = s_mask[r][1], g2 = s_mask[r][2], g3 = s_mask[r][3];
            u64 n0, n1, n2, n3;
            if (r < HH - 2) {
                n0 = s_mask[r + 1][0]; n1 = s_mask[r + 1][1];
                n2 = s_mask[r + 1][2]; n3 = s_mask[r + 1][3];
            } else if (r == HH - 2) {
                n0 = ~0ull; n1 = ~0ull; n2 = ~0ull; n3 = W3MASK;   // below(H-2)=gt
            } else {
                n0 = n1 = n2 = n3 = 0ull;                           // below(H-1)=0
            }
            u64 bl0 = g0 & n0, bl1 = g1 & n1, bl2 = g2 & n2, bl3 = g3 & n3;
            // right: neighbor = gt >> 1 with bit 222 forced (right(W-2)=gt); bit 223 -> 0 naturally
            u64 rt0 = (g0 >> 1) | (g1 << 63);
            u64 rt1 = (g1 >> 1) | (g2 << 63);
            u64 rt2 = (g2 >> 1) | (g3 << 63);
            u64 rt3 = (g3 >> 1) | (1ull << 30);
            rt0 &= g0; rt1 &= g1; rt2 &= g2; rt3 &= g3;
            s_b1[r][0] = bl0 ^ rt0; s_b1[r][1] = bl1 ^ rt1;
            s_b1[r][2] = bl2 ^ rt2; s_b1[r][3] = bl3 ^ rt3;
            s_b2[r][0] = bl0 & rt0; s_b2[r][1] = bl1 & rt1;
            s_b2[r][2] = bl2 & rt2; s_b2[r][3] = bl3 & rt3;
        }
        __syncthreads();

        // ---- serial raster recurrence (thread 0): rows in order, rows as 224-bit words ----
        if (tid == 0) {
            u64 p10 = ~0ull, p11 = ~0ull, p12 = ~0ull, p13 = W3MASK;  // virtual row -1 = ones
            u64 p20 = 0, p21 = 0, p22 = 0, p23 = 0;                   // virtual row -2 = zeros
            u64 cm0 = 0, cm1 = 0, cm2 = 0, cm3 = 0;
            int hmin = -1, hmax = -1;
            for (int r = 0; r < HH; r++) {
                u64 ab0 = p10 & p20, ab1 = p11 & p21, ab2 = p12 & p22, ab3 = p13 & p23;
                u64 b10 = s_b1[r][0], b11 = s_b1[r][1], b12 = s_b1[r][2], b13 = s_b1[r][3];
                u64 b20 = s_b2[r][0], b21 = s_b2[r][1], b22 = s_b2[r][2], b23 = s_b2[r][3];
                // a = base + above; O: a>=2, P: a==1
                u64 O0 = b20 | (b10 & ab0), O1 = b21 | (b11 & ab1);
                u64 O2 = b22 | (b12 & ab2), O3 = b23 | (b13 & ab3);
                u64 P0 = (b10 ^ ab0) & ~b20, P1 = (b11 ^ ab1) & ~b21;
                u64 P2 = (b12 ^ ab2) & ~b22, P3 = (b13 ^ ab3) & ~b23;
                // run starts: S = P & ~(P<<1)   (virtual P(-1)=0)
                u64 t0 = P0 << 1;
                u64 t1 = (P1 << 1) | (P0 >> 63);
                u64 t2 = (P2 << 1) | (P1 >> 63);
                u64 t3 = (P3 << 1) | (P2 >> 63);
                u64 S0 = P0 & ~t0, S1 = P1 & ~t1, S2 = P2 & ~t2, S3 = P3 & ~t3;
                u64 F0 = 0, F1 = 0, F2 = 0, F3 = 0;
                if (P0 | P1 | P2 | P3) {
                    // fixpoint: fill runs whose carry-in n(s-1)&n(s-2)==1
                    // virtual n(-1)=1, n(-2)=0
                    for (int it = 0; it < 256; it++) {
                        u64 k0 = O0 | F0, k1 = O1 | F1, k2 = O2 | F2, k3 = O3 | F3;
                        u64 a0 = (k0 << 1) | 1ull;
                        u64 a1 = (k1 << 1) | (k0 >> 63);
                        u64 a2 = (k2 << 1) | (k1 >> 63);
                        u64 a3 = (k3 << 1) | (k2 >> 63);
                        u64 c0 = (k0 << 2) | 2ull;
                        u64 c1 = (k1 << 2) | (k0 >> 62);
                        u64 c2 = (k2 << 2) | (k1 >> 62);
                        u64 c3 = (k3 << 2) | (k2 >> 62);
                        u64 gs0 = S0 & a0 & c0, gs1 = S1 & a1 & c1;
                        u64 gs2 = S2 & a2 & c2, gs3 = S3 & a3 & c3;
                        // 224-bit add: sum = P + gs (ripple flips seeded runs to 0)
                        u64 s0 = P0 + gs0; u64 cy = (s0 < P0);
                        u64 u1 = P1 + cy; u64 cA = (u1 < P1);
                        u64 s1 = u1 + gs1; cy = cA | (s1 < u1);
                        u64 u2 = P2 + cy; cA = (u2 < P2);
                        u64 s2 = u2 + gs2; cy = cA | (s2 < u2);
                        u64 s3 = P3 + gs3 + cy;
                        u64 Fn0 = P0 & ~s0, Fn1 = P1 & ~s1, Fn2 = P2 & ~s2, Fn3 = P3 & ~s3;
                        u64 ch = (Fn0 ^ F0) | (Fn1 ^ F1) | (Fn2 ^ F2) | (Fn3 ^ F3);
                        F0 = Fn0; F1 = Fn1; F2 = Fn2; F3 = Fn3;
                        if (!ch) break;
                    }
                }
                u64 nn0 = O0 | F0, nn1 = O1 | F1, nn2 = O2 | F2, nn3 = O3 | F3;
                s_n[r][0] = nn0; s_n[r][1] = nn1; s_n[r][2] = nn2; s_n[r][3] = nn3;
                if (nn0 | nn1 | nn2 | nn3) {
                    if (hmin < 0) hmin = r;
                    hmax = r;
                    cm0 |= nn0; cm1 |= nn1; cm2 |= nn2; cm3 |= nn3;
                }
                p20 = p10; p21 = p11; p22 = p12; p23 = p13;
                p10 = nn0; p11 = nn1; p12 = nn2; p13 = nn3;
            }
            int wmin, wmax;
            if (hmin < 0) {   // empty: argmax-of-all-False semantics
                hmin = 0; hmax = HH - 1; wmin = 0; wmax = WW - 1;
            } else {
                if (cm0)      wmin = __ffsll((long long)cm0) - 1;
                else if (cm1) wmin = 64  + __ffsll((long long)cm1) - 1;
                else if (cm2) wmin = 128 + __ffsll((long long)cm2) - 1;
                else          wmin = 192 + __ffsll((long long)cm3) - 1;
                if (cm3)      wmax = 255 - __clzll((long long)cm3);
                else if (cm2) wmax = 191 - __clzll((long long)cm2);
                else if (cm1) wmax = 127 - __clzll((long long)cm1);
                else          wmax = 63  - __clzll((long long)cm0);
            }
            // rect columns [wmin, wmax)  (wmax EXCLUSIVE, matching reference slice)
#pragma unroll
            for (int j = 0; j < 4; j++)
                s_rect[j] = mask_lt(wmax, j) & ~mask_lt(wmin, j);
            s_hmin = hmin; s_hmax = hmax;
        }
        __syncthreads();

        // ---- parallel: new mask = n | rect ----
        {
            int hmin = s_hmin, hmax = s_hmax;
            u64 rc0 = s_rect[0], rc1 = s_rect[1], rc2 = s_rect[2], rc3 = s_rect[3];
            for (int r = tid; r < HH; r += 128) {
                bool in = (r >= hmin) && (r <= hmax);
                u64 m0 = in ? rc0 : 0ull, m1 = in ? rc1 : 0ull;
                u64 m2 = in ? rc2 : 0ull, m3 = in ? rc3 : 0ull;
                s_mask[r][0] = s_n[r][0] | m0;
                s_mask[r][1] = s_n[r][1] | m1;
                s_mask[r][2] = s_n[r][2] | m2;
                s_mask[r][3] = s_n[r][3] | m3;
            }
        }
        __syncthreads();
    }

    // ---- unpack to float ----
    for (int r = warp; r < HH; r += 4) {
#pragma unroll
        for (int c = 0; c < 7; c++) {
            int w = c * 32 + lane;
            oi[r * WW + w] = (float)((s_mask[r][w >> 6] >> (w & 63)) & 1ull);
        }
    }
}

extern "C" void kernel_launch(void* const* d_in, const int* in_sizes, int n_in,
                              void* d_out, int out_size) {
    const float* x = (const float*)d_in[0];
    float* out = (float*)d_out;
    int nimg = in_sizes[0] / IMG;   // B*C = 8
    mask_ca_kernel<<<nimg, 128>>>(x, out);
}

// round 2
// speedup vs baseline: 2.4035x; 2.4035x over previous
#include <cuda_runtime.h>

typedef unsigned long long u64;

#define HH 224
#define WW 224
#define IMG (HH * WW)
#define NPASS 9
#define W3MASK 0xFFFFFFFFull

// bits 0..k-1 of word j (j*64 .. j*64+63) of a 224-bit mask
__device__ __forceinline__ u64 mask_lt(int k, int j) {
    int lo = j * 64;
    if (k <= lo) return 0ull;
    if (k >= lo + 64) return ~0ull;
    return (1ull << (k - lo)) - 1ull;
}

__global__ __launch_bounds__(128) void mask_ca_kernel(const float* __restrict__ x,
                                                      float* __restrict__ out) {
    __shared__ u64 s_mask[HH][4];   // current mask (post rect-fill)
    __shared__ u64 s_b1[HH][4];     // base == exactly one of below/right
    __shared__ u64 s_b2[HH][4];     // base == both
    __shared__ u64 s_n[HH][4];      // serial-scan output (pre rect-fill)
    __shared__ u64 s_rect[4];
    __shared__ int s_hmin, s_hmax, s_changed;

    const int tid  = threadIdx.x;
    const int lane = tid & 31;
    const int warp = tid >> 5;
    const float* xi = x + (size_t)blockIdx.x * IMG;
    float* oi = out + (size_t)blockIdx.x * IMG;

    // ---- pack input: threshold > 0.8 into 224-bit rows (4x u64) ----
    for (int r = warp; r < HH; r += 4) {
        const float* row = xi + r * WW;
        unsigned b[7];
#pragma unroll
        for (int c = 0; c < 7; c++)
            b[c] = __ballot_sync(0xFFFFFFFFu, row[c * 32 + lane] > 0.8f);
        if (lane == 0) {
            s_mask[r][0] = (u64)b[0] | ((u64)b[1] << 32);
            s_mask[r][1] = (u64)b[2] | ((u64)b[3] << 32);
            s_mask[r][2] = (u64)b[4] | ((u64)b[5] << 32);
            s_mask[r][3] = (u64)b[6];
        }
    }
    __syncthreads();

    // ---- initial b1/b2 from packed input ----
    for (int r = tid; r < HH; r += 128) {
        u64 g0 = s_mask[r][0], g1 = s_mask[r][1], g2 = s_mask[r][2], g3 = s_mask[r][3];
        u64 n0, n1, n2, n3;
        if (r < HH - 2) {
            n0 = s_mask[r + 1][0]; n1 = s_mask[r + 1][1];
            n2 = s_mask[r + 1][2]; n3 = s_mask[r + 1][3];
        } else if (r == HH - 2) {
            n0 = ~0ull; n1 = ~0ull; n2 = ~0ull; n3 = W3MASK;   // below(H-2)=gt
        } else {
            n0 = n1 = n2 = n3 = 0ull;                           // below(H-1)=0
        }
        u64 bl0 = g0 & n0, bl1 = g1 & n1, bl2 = g2 & n2, bl3 = g3 & n3;
        u64 rt0 = ((g0 >> 1) | (g1 << 63)) & g0;
        u64 rt1 = ((g1 >> 1) | (g2 << 63)) & g1;
        u64 rt2 = ((g2 >> 1) | (g3 << 63)) & g2;
        u64 rt3 = ((g3 >> 1) | (1ull << 30)) & g3;   // right(W-2)=gt, right(W-1)=0
        s_b1[r][0] = bl0 ^ rt0; s_b1[r][1] = bl1 ^ rt1;
        s_b1[r][2] = bl2 ^ rt2; s_b1[r][3] = bl3 ^ rt3;
        s_b2[r][0] = bl0 & rt0; s_b2[r][1] = bl1 & rt1;
        s_b2[r][2] = bl2 & rt2; s_b2[r][3] = bl3 & rt3;
    }
    __syncthreads();

    for (int pass = 0; pass < NPASS; pass++) {
        // ---- serial raster recurrence (thread 0) ----
        if (tid == 0) {
            s_changed = 0;
            u64 p10 = ~0ull, p11 = ~0ull, p12 = ~0ull, p13 = W3MASK;  // virtual row -1 = ones
            u64 p20 = 0, p21 = 0, p22 = 0, p23 = 0;                   // virtual row -2 = zeros
            u64 cm0 = 0, cm1 = 0, cm2 = 0, cm3 = 0;
            int hmin = -1, hmax = -1;
            for (int r = 0; r < HH; r++) {
                u64 ab0 = p10 & p20, ab1 = p11 & p21, ab2 = p12 & p22, ab3 = p13 & p23;
                u64 b10 = s_b1[r][0], b11 = s_b1[r][1], b12 = s_b1[r][2], b13 = s_b1[r][3];
                u64 b20 = s_b2[r][0], b21 = s_b2[r][1], b22 = s_b2[r][2], b23 = s_b2[r][3];
                // a = base + above; O: a>=2, P: a==1
                u64 O0 = b20 | (b10 & ab0), O1 = b21 | (b11 & ab1);
                u64 O2 = b22 | (b12 & ab2), O3 = b23 | (b13 & ab3);
                u64 P0 = (b10 ^ ab0) & ~b20, P1 = (b11 ^ ab1) & ~b21;
                u64 P2 = (b12 ^ ab2) & ~b22, P3 = (b13 ^ ab3) & ~b23;
                u64 F0 = 0, F1 = 0, F2 = 0, F3 = 0;
                if (P0 | P1 | P2 | P3) {
                    // run starts: S = P & ~(P<<1)   (virtual P(-1)=0)
                    u64 S0 = P0 & ~(P0 << 1);
                    u64 S1 = P1 & ~((P1 << 1) | (P0 >> 63));
                    u64 S2 = P2 & ~((P2 << 1) | (P1 >> 63));
                    u64 S3 = P3 & ~((P3 << 1) | (P2 >> 63));
                    // fixpoint: fill runs whose carry-in n(s-1)&n(s-2)==1
                    // virtual n(-1)=1, n(-2)=0
                    for (int it = 0; it < 256; it++) {
                        u64 k0 = O0 | F0, k1 = O1 | F1, k2 = O2 | F2, k3 = O3 | F3;
                        u64 a0 = (k0 << 1) | 1ull;
                        u64 a1 = (k1 << 1) | (k0 >> 63);
                        u64 a2 = (k2 << 1) | (k1 >> 63);
                        u64 a3 = (k3 << 1) | (k2 >> 63);
                        u64 c0 = (k0 << 2) | 2ull;
                        u64 c1 = (k1 << 2) | (k0 >> 62);
                        u64 c2 = (k2 << 2) | (k1 >> 62);
                        u64 c3 = (k3 << 2) | (k2 >> 62);
                        u64 gs0 = S0 & a0 & c0, gs1 = S1 & a1 & c1;
                        u64 gs2 = S2 & a2 & c2, gs3 = S3 & a3 & c3;
                        // 224-bit add: sum = P + gs (ripple flips seeded runs to 0)
                        u64 s0 = P0 + gs0; u64 cy = (s0 < P0);
                        u64 u1 = P1 + cy; u64 cA = (u1 < P1);
                        u64 s1 = u1 + gs1; cy = cA | (s1 < u1);
                        u64 u2 = P2 + cy; cA = (u2 < P2);
                        u64 s2 = u2 + gs2; cy = cA | (s2 < u2);
                        u64 s3 = P3 + gs3 + cy;
                        u64 Fn0 = P0 & ~s0, Fn1 = P1 & ~s1, Fn2 = P2 & ~s2, Fn3 = P3 & ~s3;
                        u64 ch = (Fn0 ^ F0) | (Fn1 ^ F1) | (Fn2 ^ F2) | (Fn3 ^ F3);
                        F0 = Fn0; F1 = Fn1; F2 = Fn2; F3 = Fn3;
                        if (!ch) break;
                    }
                }
                u64 nn0 = O0 | F0, nn1 = O1 | F1, nn2 = O2 | F2, nn3 = O3 | F3;
                s_n[r][0] = nn0; s_n[r][1] = nn1; s_n[r][2] = nn2; s_n[r][3] = nn3;
                if (nn0 | nn1 | nn2 | nn3) {
                    if (hmin < 0) hmin = r;
                    hmax = r;
                    cm0 |= nn0; cm1 |= nn1; cm2 |= nn2; cm3 |= nn3;
                }
                p20 = p10; p21 = p11; p22 = p12; p23 = p13;
                p10 = nn0; p11 = nn1; p12 = nn2; p13 = nn3;
            }
            int wmin, wmax;
            if (hmin < 0) {   // empty: argmax-of-all-False semantics
                hmin = 0; hmax = HH - 1; wmin = 0; wmax = WW - 1;
            } else {
                if (cm0)      wmin = __ffsll((long long)cm0) - 1;
                else if (cm1) wmin = 64  + __ffsll((long long)cm1) - 1;
                else if (cm2) wmin = 128 + __ffsll((long long)cm2) - 1;
                else          wmin = 192 + __ffsll((long long)cm3) - 1;
                if (cm3)      wmax = 255 - __clzll((long long)cm3);
                else if (cm2) wmax = 191 - __clzll((long long)cm2);
                else if (cm1) wmax = 127 - __clzll((long long)cm1);
                else          wmax = 63  - __clzll((long long)cm0);
            }
            // rect columns [wmin, wmax)  (wmax EXCLUSIVE, matching reference slice)
#pragma unroll
            for (int j = 0; j < 4; j++)
                s_rect[j] = mask_lt(wmax, j) & ~mask_lt(wmin, j);
            s_hmin = hmin; s_hmax = hmax;
        }
        __syncthreads();

        // ---- fused parallel phase: apply rect + change-detect + next-pass b1/b2 ----
        {
            const int hmin = s_hmin, hmax = s_hmax;
            const u64 rc0 = s_rect[0], rc1 = s_rect[1], rc2 = s_rect[2], rc3 = s_rect[3];
            u64 diff = 0;
            for (int r = tid; r < HH; r += 128) {
                bool in = (r >= hmin) && (r <= hmax);
                u64 g0 = s_n[r][0] | (in ? rc0 : 0ull);
                u64 g1 = s_n[r][1] | (in ? rc1 : 0ull);
                u64 g2 = s_n[r][2] | (in ? rc2 : 0ull);
                u64 g3 = s_n[r][3] | (in ? rc3 : 0ull);
                diff |= (g0 ^ s_mask[r][0]) | (g1 ^ s_mask[r][1])
                      | (g2 ^ s_mask[r][2]) | (g3 ^ s_mask[r][3]);
                s_mask[r][0] = g0; s_mask[r][1] = g1;
                s_mask[r][2] = g2; s_mask[r][3] = g3;
                // reconstruct next row's new mask locally (s_n written before barrier)
                u64 n0, n1, n2, n3;
                if (r < HH - 2) {
                    bool in1 = (r + 1 >= hmin) && (r + 1 <= hmax);
                    n0 = s_n[r + 1][0] | (in1 ? rc0 : 0ull);
                    n1 = s_n[r + 1][1] | (in1 ? rc1 : 0ull);
                    n2 = s_n[r + 1][2] | (in1 ? rc2 : 0ull);
                    n3 = s_n[r + 1][3] | (in1 ? rc3 : 0ull);
                } else if (r == HH - 2) {
                    n0 = ~0ull; n1 = ~0ull; n2 = ~0ull; n3 = W3MASK;   // below(H-2)=gt
                } else {
                    n0 = n1 = n2 = n3 = 0ull;                           // below(H-1)=0
                }
                u64 bl0 = g0 & n0, bl1 = g1 & n1, bl2 = g2 & n2, bl3 = g3 & n3;
                u64 rt0 = ((g0 >> 1) | (g1 << 63)) & g0;
                u64 rt1 = ((g1 >> 1) | (g2 << 63)) & g1;
                u64 rt2 = ((g2 >> 1) | (g3 << 63)) & g2;
                u64 rt3 = ((g3 >> 1) | (1ull << 30)) & g3;
                s_b1[r][0] = bl0 ^ rt0; s_b1[r][1] = bl1 ^ rt1;
                s_b1[r][2] = bl2 ^ rt2; s_b1[r][3] = bl3 ^ rt3;
                s_b2[r][0] = bl0 & rt0; s_b2[r][1] = bl1 & rt1;
                s_b2[r][2] = bl2 & rt2; s_b2[r][3] = bl3 & rt3;
            }
            if (diff) s_changed = 1;   // benign multi-writer race (all write 1)
        }
        __syncthreads();

        // converged: pass(m)==m, all remaining passes are identity
        if (!s_changed) break;
    }

    // ---- unpack to float ----
    for (int r = warp; r < HH; r += 4) {
#pragma unroll
        for (int c = 0; c < 7; c++) {
            int w = c * 32 + lane;
            oi[r * WW + w] = (float)((s_mask[r][w >> 6] >> (w & 63)) & 1ull);
        }
    }
}

extern "C" void kernel_launch(void* const* d_in, const int* in_sizes, int n_in,
                              void* d_out, int out_size) {
    const float* x = (const float*)d_in[0];
    float* out = (float*)d_out;
    int nimg = in_sizes[0] / IMG;   // B*C = 8
    mask_ca_kernel<<<nimg, 128>>>(x, out);
}

// round 3
// speedup vs baseline: 2.8380x; 1.1808x over previous
#include <cuda_runtime.h>

typedef unsigned long long u64;

#define HH 224
#define WW 224
#define IMG (HH * WW)
#define NPASS 9
#define W3MASK 0xFFFFFFFFull

// bits 0..k-1 of word j (j*64 .. j*64+63) of a 224-bit mask
__device__ __forceinline__ u64 mask_lt(int k, int j) {
    int lo = j * 64;
    if (k <= lo) return 0ull;
    if (k >= lo + 64) return ~0ull;
    return (1ull << (k - lo)) - 1ull;
}

__global__ __launch_bounds__(128) void mask_ca_kernel(const float* __restrict__ x,
                                                      float* __restrict__ out) {
    __shared__ u64 s_mask[HH][4];   // current mask (post rect-fill)
    __shared__ u64 s_b1[HH][4];     // base == exactly one of below/right
    __shared__ u64 s_b2[HH][4];     // base == both
    __shared__ u64 s_n[HH][4];      // serial-scan output (pre rect-fill)
    __shared__ u64 s_rect[4];
    __shared__ int s_hmin, s_hmax, s_changed;

    const int tid  = threadIdx.x;
    const int lane = tid & 31;
    const int warp = tid >> 5;
    const float* xi = x + (size_t)blockIdx.x * IMG;
    float* oi = out + (size_t)blockIdx.x * IMG;

    // ---- pack input: threshold > 0.8 into 224-bit rows (4x u64) ----
    for (int r = warp; r < HH; r += 4) {
        const float* row = xi + r * WW;
        unsigned b[7];
#pragma unroll
        for (int c = 0; c < 7; c++)
            b[c] = __ballot_sync(0xFFFFFFFFu, row[c * 32 + lane] > 0.8f);
        if (lane == 0) {
            s_mask[r][0] = (u64)b[0] | ((u64)b[1] << 32);
            s_mask[r][1] = (u64)b[2] | ((u64)b[3] << 32);
            s_mask[r][2] = (u64)b[4] | ((u64)b[5] << 32);
            s_mask[r][3] = (u64)b[6];
        }
    }
    __syncthreads();

    // ---- initial b1/b2 from packed input ----
    for (int r = tid; r < HH; r += 128) {
        u64 g0 = s_mask[r][0], g1 = s_mask[r][1], g2 = s_mask[r][2], g3 = s_mask[r][3];
        u64 n0, n1, n2, n3;
        if (r < HH - 2) {
            n0 = s_mask[r + 1][0]; n1 = s_mask[r + 1][1];
            n2 = s_mask[r + 1][2]; n3 = s_mask[r + 1][3];
        } else if (r == HH - 2) {
            n0 = ~0ull; n1 = ~0ull; n2 = ~0ull; n3 = W3MASK;   // below(H-2)=gt
        } else {
            n0 = n1 = n2 = n3 = 0ull;                           // below(H-1)=0
        }
        u64 bl0 = g0 & n0, bl1 = g1 & n1, bl2 = g2 & n2, bl3 = g3 & n3;
        u64 rt0 = ((g0 >> 1) | (g1 << 63)) & g0;
        u64 rt1 = ((g1 >> 1) | (g2 << 63)) & g1;
        u64 rt2 = ((g2 >> 1) | (g3 << 63)) & g2;
        u64 rt3 = ((g3 >> 1) | (1ull << 30)) & g3;   // right(W-2)=gt, right(W-1)=0
        s_b1[r][0] = bl0 ^ rt0; s_b1[r][1] = bl1 ^ rt1;
        s_b1[r][2] = bl2 ^ rt2; s_b1[r][3] = bl3 ^ rt3;
        s_b2[r][0] = bl0 & rt0; s_b2[r][1] = bl1 & rt1;
        s_b2[r][2] = bl2 & rt2; s_b2[r][3] = bl3 & rt3;
    }
    __syncthreads();

    for (int pass = 0; pass < NPASS; pass++) {
        // ---- serial raster recurrence (thread 0) ----
        if (tid == 0) {
            s_changed = 0;
            u64 p10 = ~0ull, p11 = ~0ull, p12 = ~0ull, p13 = W3MASK;  // virtual row -1 = ones
            u64 p20 = 0, p21 = 0, p22 = 0, p23 = 0;                   // virtual row -2 = zeros
            u64 cm0 = 0, cm1 = 0, cm2 = 0, cm3 = 0;
            int hmin = -1, hmax = -1;
            // memo: nn is a pure function of (b1, b2, ab). Cache the previous
            // slow-path triple + its result; identical consecutive rows reuse it.
            u64 qb10 = 0, qb11 = 0, qb12 = 0, qb13 = 0;
            u64 qb20 = 0, qb21 = 0, qb22 = 0, qb23 = 0;
            u64 qab0 = 0, qab1 = 0, qab2 = 0, qab3 = 0;
            u64 qn0 = 0, qn1 = 0, qn2 = 0, qn3 = 0;
            bool havep = false;
            for (int r = 0; r < HH; r++) {
                u64 ab0 = p10 & p20, ab1 = p11 & p21, ab2 = p12 & p22, ab3 = p13 & p23;
                u64 b10 = s_b1[r][0], b11 = s_b1[r][1], b12 = s_b1[r][2], b13 = s_b1[r][3];
                u64 b20 = s_b2[r][0], b21 = s_b2[r][1], b22 = s_b2[r][2], b23 = s_b2[r][3];
                u64 nn0, nn1, nn2, nn3;
                u64 dmem = (b10 ^ qb10) | (b11 ^ qb11) | (b12 ^ qb12) | (b13 ^ qb13)
                         | (b20 ^ qb20) | (b21 ^ qb21) | (b22 ^ qb22) | (b23 ^ qb23)
                         | (ab0 ^ qab0) | (ab1 ^ qab1) | (ab2 ^ qab2) | (ab3 ^ qab3);
                if (havep && dmem == 0ull) {
                    nn0 = qn0; nn1 = qn1; nn2 = qn2; nn3 = qn3;
                } else {
                    // a = base + above; O: a>=2, P: a==1
                    u64 O0 = b20 | (b10 & ab0), O1 = b21 | (b11 & ab1);
                    u64 O2 = b22 | (b12 & ab2), O3 = b23 | (b13 & ab3);
                    u64 P0 = (b10 ^ ab0) & ~b20, P1 = (b11 ^ ab1) & ~b21;
                    u64 P2 = (b12 ^ ab2) & ~b22, P3 = (b13 ^ ab3) & ~b23;
                    u64 F0 = 0, F1 = 0, F2 = 0, F3 = 0;
                    if (P0 | P1 | P2 | P3) {
                        // run starts: S = P & ~(P<<1)   (virtual P(-1)=0)
                        u64 S0 = P0 & ~(P0 << 1);
                        u64 S1 = P1 & ~((P1 << 1) | (P0 >> 63));
                        u64 S2 = P2 & ~((P2 << 1) | (P1 >> 63));
                        u64 S3 = P3 & ~((P3 << 1) | (P2 >> 63));
                        // seed: runs whose carry-in n(s-1)&n(s-2)==1 under k=O
                        // virtual n(-1)=1, n(-2)=0
                        u64 gs0 = S0 & ((O0 << 1) | 1ull) & ((O0 << 2) | 2ull);
                        u64 gs1 = S1 & ((O1 << 1) | (O0 >> 63)) & ((O1 << 2) | (O0 >> 62));
                        u64 gs2 = S2 & ((O2 << 1) | (O1 >> 63)) & ((O2 << 2) | (O1 >> 62));
                        u64 gs3 = S3 & ((O3 << 1) | (O2 >> 63)) & ((O3 << 2) | (O2 >> 62));
                        if (gs0 | gs1 | gs2 | gs3) {
                            // gs is monotone across iterations; F is a pure
                            // function of gs, so iterate on gs itself.
                            for (int it = 0; it < 256; it++) {
                                // 224-bit add: sum = P + gs (ripple flips seeded runs to 0)
                                u64 s0 = P0 + gs0; u64 cy = (s0 < P0);
                                u64 u1 = P1 + cy; u64 cA = (u1 < P1);
                                u64 s1 = u1 + gs1; cy = cA | (s1 < u1);
                                u64 u2 = P2 + cy; cA = (u2 < P2);
                                u64 s2 = u2 + gs2; cy = cA | (s2 < u2);
                                u64 s3 = P3 + gs3 + cy;
                                F0 = P0 & ~s0; F1 = P1 & ~s1; F2 = P2 & ~s2; F3 = P3 & ~s3;
                                u64 k0 = O0 | F0, k1 = O1 | F1, k2 = O2 | F2, k3 = O3 | F3;
                                u64 gn0 = S0 & ((k0 << 1) | 1ull) & ((k0 << 2) | 2ull);
                                u64 gn1 = S1 & ((k1 << 1) | (k0 >> 63)) & ((k1 << 2) | (k0 >> 62));
                                u64 gn2 = S2 & ((k2 << 1) | (k1 >> 63)) & ((k2 << 2) | (k1 >> 62));
                                u64 gn3 = S3 & ((k3 << 1) | (k2 >> 63)) & ((k3 << 2) | (k2 >> 62));
                                u64 ch = (gn0 ^ gs0) | (gn1 ^ gs1) | (gn2 ^ gs2) | (gn3 ^ gs3);
                                if (!ch) break;
                                gs0 = gn0; gs1 = gn1; gs2 = gn2; gs3 = gn3;
                            }
                        }
                    }
                    nn0 = O0 | F0; nn1 = O1 | F1; nn2 = O2 | F2; nn3 = O3 | F3;
                    qb10 = b10; qb11 = b11; qb12 = b12; qb13 = b13;
                    qb20 = b20; qb21 = b21; qb22 = b22; qb23 = b23;
                    qab0 = ab0; qab1 = ab1; qab2 = ab2; qab3 = ab3;
                    qn0 = nn0; qn1 = nn1; qn2 = nn2; qn3 = nn3;
                    havep = true;
                }
                s_n[r][0] = nn0; s_n[r][1] = nn1; s_n[r][2] = nn2; s_n[r][3] = nn3;
                if (nn0 | nn1 | nn2 | nn3) {
                    if (hmin < 0) hmin = r;
                    hmax = r;
                    cm0 |= nn0; cm1 |= nn1; cm2 |= nn2; cm3 |= nn3;
                }
                p20 = p10; p21 = p11; p22 = p12; p23 = p13;
                p10 = nn0; p11 = nn1; p12 = nn2; p13 = nn3;
            }
            int wmin, wmax;
            if (hmin < 0) {   // empty: argmax-of-all-False semantics
                hmin = 0; hmax = HH - 1; wmin = 0; wmax = WW - 1;
            } else {
                if (cm0)      wmin = __ffsll((long long)cm0) - 1;
                else if (cm1) wmin = 64  + __ffsll((long long)cm1) - 1;
                else if (cm2) wmin = 128 + __ffsll((long long)cm2) - 1;
                else          wmin = 192 + __ffsll((long long)cm3) - 1;
                if (cm3)      wmax = 255 - __clzll((long long)cm3);
                else if (cm2) wmax = 191 - __clzll((long long)cm2);
                else if (cm1) wmax = 127 - __clzll((long long)cm1);
                else          wmax = 63  - __clzll((long long)cm0);
            }
            // rect columns [wmin, wmax)  (wmax EXCLUSIVE, matching reference slice)
#pragma unroll
            for (int j = 0; j < 4; j++)
                s_rect[j] = mask_lt(wmax, j) & ~mask_lt(wmin, j);
            s_hmin = hmin; s_hmax = hmax;
        }
        __syncthreads();

        // ---- fused parallel phase: apply rect + change-detect + next-pass b1/b2 ----
        {
            const int hmin = s_hmin, hmax = s_hmax;
            const u64 rc0 = s_rect[0], rc1 = s_rect[1], rc2 = s_rect[2], rc3 = s_rect[3];
            u64 diff = 0;
            for (int r = tid; r < HH; r += 128) {
                bool in = (r >= hmin) && (r <= hmax);
                u64 g0 = s_n[r][0] | (in ? rc0 : 0ull);
                u64 g1 = s_n[r][1] | (in ? rc1 : 0ull);
                u64 g2 = s_n[r][2] | (in ? rc2 : 0ull);
                u64 g3 = s_n[r][3] | (in ? rc3 : 0ull);
                diff |= (g0 ^ s_mask[r][0]) | (g1 ^ s_mask[r][1])
                      | (g2 ^ s_mask[r][2]) | (g3 ^ s_mask[r][3]);
                s_mask[r][0] = g0; s_mask[r][1] = g1;
                s_mask[r][2] = g2; s_mask[r][3] = g3;
                // reconstruct next row's new mask locally (s_n written before barrier)
                u64 n0, n1, n2, n3;
                if (r < HH - 2) {
                    bool in1 = (r + 1 >= hmin) && (r + 1 <= hmax);
                    n0 = s_n[r + 1][0] | (in1 ? rc0 : 0ull);
                    n1 = s_n[r + 1][1] | (in1 ? rc1 : 0ull);
                    n2 = s_n[r + 1][2] | (in1 ? rc2 : 0ull);
                    n3 = s_n[r + 1][3] | (in1 ? rc3 : 0ull);
                } else if (r == HH - 2) {
                    n0 = ~0ull; n1 = ~0ull; n2 = ~0ull; n3 = W3MASK;   // below(H-2)=gt
                } else {
                    n0 = n1 = n2 = n3 = 0ull;                           // below(H-1)=0
                }
                u64 bl0 = g0 & n0, bl1 = g1 & n1, bl2 = g2 & n2, bl3 = g3 & n3;
                u64 rt0 = ((g0 >> 1) | (g1 << 63)) & g0;
                u64 rt1 = ((g1 >> 1) | (g2 << 63)) & g1;
                u64 rt2 = ((g2 >> 1) | (g3 << 63)) & g2;
                u64 rt3 = ((g3 >> 1) | (1ull << 30)) & g3;
                s_b1[r][0] = bl0 ^ rt0; s_b1[r][1] = bl1 ^ rt1;
                s_b1[r][2] = bl2 ^ rt2; s_b1[r][3] = bl3 ^ rt3;
                s_b2[r][0] = bl0 & rt0; s_b2[r][1] = bl1 & rt1;
                s_b2[r][2] = bl2 & rt2; s_b2[r][3] = bl3 & rt3;
            }
            if (diff) s_changed = 1;   // benign multi-writer race (all write 1)
        }
        __syncthreads();

        // converged: pass(m)==m, all remaining passes are identity
        if (!s_changed) break;
    }

    // ---- unpack to float ----
    for (int r = warp; r < HH; r += 4) {
#pragma unroll
        for (int c = 0; c < 7; c++) {
            int w = c * 32 + lane;
            oi[r * WW + w] = (float)((s_mask[r][w >> 6] >> (w & 63)) & 1ull);
        }
    }
}

extern "C" void kernel_launch(void* const* d_in, const int* in_sizes, int n_in,
                              void* d_out, int out_size) {
    const float* x = (const float*)d_in[0];
    float* out = (float*)d_out;
    int nimg = in_sizes[0] / IMG;   // B*C = 8
    mask_ca_kernel<<<nimg, 128>>>(x, out);
}

// round 4
// speedup vs baseline: 3.1730x; 1.1180x over previous
#include <cuda_runtime.h>

typedef unsigned long long u64;

#define HH 224
#define WW 224
#define IMG (HH * WW)
#define NPASS 9
#define W3MASK 0xFFFFFFFFull

// bits 0..k-1 of word j (j*64 .. j*64+63) of a 224-bit mask
__device__ __forceinline__ u64 mask_lt(int k, int j) {
    int lo = j * 64;
    if (k <= lo) return 0ull;
    if (k >= lo + 64) return ~0ull;
    return (1ull << (k - lo)) - 1ull;
}

__global__ __launch_bounds__(128) void mask_ca_kernel(const float* __restrict__ x,
                                                      float* __restrict__ out) {
    __shared__ u64 s_mask[HH][4];   // current mask (post rect-fill)
    __shared__ u64 s_b1[HH][4];     // base == exactly one of below/right
    __shared__ u64 s_b2[HH][4];     // base == both
    __shared__ u64 s_n[HH][4];      // serial-scan output (pre rect-fill)
    __shared__ int s_eq[HH];        // g(r-1)==g(r)==g(r+1) (=> b(r)==b(r-1)), r in [1,H-3]
    __shared__ u64 s_rect[4];
    __shared__ int s_hmin, s_hmax, s_changed;

    const int tid  = threadIdx.x;
    const int lane = tid & 31;
    const int warp = tid >> 5;
    const float* xi = x + (size_t)blockIdx.x * IMG;
    float* oi = out + (size_t)blockIdx.x * IMG;

    // ---- pack input: threshold > 0.8 into 224-bit rows (4x u64) ----
    for (int r = warp; r < HH; r += 4) {
        const float* row = xi + r * WW;
        unsigned b[7];
#pragma unroll
        for (int c = 0; c < 7; c++)
            b[c] = __ballot_sync(0xFFFFFFFFu, row[c * 32 + lane] > 0.8f);
        if (lane == 0) {
            s_mask[r][0] = (u64)b[0] | ((u64)b[1] << 32);
            s_mask[r][1] = (u64)b[2] | ((u64)b[3] << 32);
            s_mask[r][2] = (u64)b[4] | ((u64)b[5] << 32);
            s_mask[r][3] = (u64)b[6];
        }
    }
    __syncthreads();

    // ---- initial b1/b2 + s_eq from packed input ----
    for (int r = tid; r < HH; r += 128) {
        u64 g0 = s_mask[r][0], g1 = s_mask[r][1], g2 = s_mask[r][2], g3 = s_mask[r][3];
        u64 n0, n1, n2, n3;
        if (r < HH - 2) {
            n0 = s_mask[r + 1][0]; n1 = s_mask[r + 1][1];
            n2 = s_mask[r + 1][2]; n3 = s_mask[r + 1][3];
        } else if (r == HH - 2) {
            n0 = ~0ull; n1 = ~0ull; n2 = ~0ull; n3 = W3MASK;   // below(H-2)=gt
        } else {
            n0 = n1 = n2 = n3 = 0ull;                           // below(H-1)=0
        }
        u64 bl0 = g0 & n0, bl1 = g1 & n1, bl2 = g2 & n2, bl3 = g3 & n3;
        u64 rt0 = ((g0 >> 1) | (g1 << 63)) & g0;
        u64 rt1 = ((g1 >> 1) | (g2 << 63)) & g1;
        u64 rt2 = ((g2 >> 1) | (g3 << 63)) & g2;
        u64 rt3 = ((g3 >> 1) | (1ull << 30)) & g3;   // right(W-2)=gt, right(W-1)=0
        s_b1[r][0] = bl0 ^ rt0; s_b1[r][1] = bl1 ^ rt1;
        s_b1[r][2] = bl2 ^ rt2; s_b1[r][3] = bl3 ^ rt3;
        s_b2[r][0] = bl0 & rt0; s_b2[r][1] = bl1 & rt1;
        s_b2[r][2] = bl2 & rt2; s_b2[r][3] = bl3 & rt3;
        int eqv = 0;
        if (r >= 1 && r <= HH - 3) {
            u64 m0 = s_mask[r - 1][0], m1 = s_mask[r - 1][1];
            u64 m2 = s_mask[r - 1][2], m3 = s_mask[r - 1][3];
            u64 d = (m0 ^ g0) | (m1 ^ g1) | (m2 ^ g2) | (m3 ^ g3)
                  | (g0 ^ n0) | (g1 ^ n1) | (g2 ^ n2) | (g3 ^ n3);
            eqv = (d == 0ull);
        }
        s_eq[r] = eqv;
    }
    __syncthreads();

    for (int pass = 0; pass < NPASS; pass++) {
        // ---- serial raster recurrence (thread 0) ----
        if (tid == 0) {
            s_changed = 0;
            u64 p10 = ~0ull, p11 = ~0ull, p12 = ~0ull, p13 = W3MASK;  // virtual row -1 = ones
            u64 p20 = 0, p21 = 0, p22 = 0, p23 = 0;                   // virtual row -2 = zeros
            u64 cm0 = 0, cm1 = 0, cm2 = 0, cm3 = 0;
            int hmin = -1, hmax = -1;
            int e1 = 0, e2 = 0;   // nn(r-1)==nn(r-2), nn(r-2)==nn(r-3)
            int nzflag = 0;       // nn(r-1) nonzero
            for (int r = 0; r < HH; r++) {
                if (e1 & e2 & s_eq[r]) {
                    // hit: b(r)==b(r-1) and ab(r)==ab(r-1) => nn(r)==nn(r-1)==p1
                    s_n[r][0] = p10; s_n[r][1] = p11; s_n[r][2] = p12; s_n[r][3] = p13;
                    if (nzflag) hmax = r;          // hmin/cm already reflect this value
                    p20 = p10; p21 = p11; p22 = p12; p23 = p13;   // p1 unchanged
                    e2 = e1; e1 = 1;
                    continue;
                }
                u64 ab0 = p10 & p20, ab1 = p11 & p21, ab2 = p12 & p22, ab3 = p13 & p23;
                u64 b10 = s_b1[r][0], b11 = s_b1[r][1], b12 = s_b1[r][2], b13 = s_b1[r][3];
                u64 b20 = s_b2[r][0], b21 = s_b2[r][1], b22 = s_b2[r][2], b23 = s_b2[r][3];
                // a = base + above; O: a>=2, P: a==1
                u64 O0 = b20 | (b10 & ab0), O1 = b21 | (b11 & ab1);
                u64 O2 = b22 | (b12 & ab2), O3 = b23 | (b13 & ab3);
                u64 P0 = (b10 ^ ab0) & ~b20, P1 = (b11 ^ ab1) & ~b21;
                u64 P2 = (b12 ^ ab2) & ~b22, P3 = (b13 ^ ab3) & ~b23;
                u64 F0 = 0, F1 = 0, F2 = 0, F3 = 0;
                if (P0 | P1 | P2 | P3) {
                    // run starts: S = P & ~(P<<1)   (virtual P(-1)=0)
                    u64 S0 = P0 & ~(P0 << 1);
                    u64 S1 = P1 & ~((P1 << 1) | (P0 >> 63));
                    u64 S2 = P2 & ~((P2 << 1) | (P1 >> 63));
                    u64 S3 = P3 & ~((P3 << 1) | (P2 >> 63));
                    // seed: runs whose carry-in n(s-1)&n(s-2)==1 under k=O
                    // virtual n(-1)=1, n(-2)=0
                    u64 gs0 = S0 & ((O0 << 1) | 1ull) & ((O0 << 2) | 2ull);
                    u64 gs1 = S1 & ((O1 << 1) | (O0 >> 63)) & ((O1 << 2) | (O0 >> 62));
                    u64 gs2 = S2 & ((O2 << 1) | (O1 >> 63)) & ((O2 << 2) | (O1 >> 62));
                    u64 gs3 = S3 & ((O3 << 1) | (O2 >> 63)) & ((O3 << 2) | (O2 >> 62));
                    if (gs0 | gs1 | gs2 | gs3) {
                        // gs monotone; F is a pure function of gs -> iterate on gs
                        for (int it = 0; it < 256; it++) {
                            // 224-bit add: sum = P + gs (ripple flips seeded runs to 0)
                            u64 s0 = P0 + gs0; u64 cy = (s0 < P0);
                            u64 u1 = P1 + cy; u64 cA = (u1 < P1);
                            u64 s1 = u1 + gs1; cy = cA | (s1 < u1);
                            u64 u2 = P2 + cy; cA = (u2 < P2);
                            u64 s2 = u2 + gs2; cy = cA | (s2 < u2);
                            u64 s3 = P3 + gs3 + cy;
                            F0 = P0 & ~s0; F1 = P1 & ~s1; F2 = P2 & ~s2; F3 = P3 & ~s3;
                            u64 k0 = O0 | F0, k1 = O1 | F1, k2 = O2 | F2, k3 = O3 | F3;
                            u64 gn0 = S0 & ((k0 << 1) | 1ull) & ((k0 << 2) | 2ull);
                            u64 gn1 = S1 & ((k1 << 1) | (k0 >> 63)) & ((k1 << 2) | (k0 >> 62));
                            u64 gn2 = S2 & ((k2 << 1) | (k1 >> 63)) & ((k2 << 2) | (k1 >> 62));
                            u64 gn3 = S3 & ((k3 << 1) | (k2 >> 63)) & ((k3 << 2) | (k2 >> 62));
                            u64 ch = (gn0 ^ gs0) | (gn1 ^ gs1) | (gn2 ^ gs2) | (gn3 ^ gs3);
                            if (!ch) break;
                            gs0 = gn0; gs1 = gn1; gs2 = gn2; gs3 = gn3;
                        }
                    }
                }
                u64 nn0 = O0 | F0, nn1 = O1 | F1, nn2 = O2 | F2, nn3 = O3 | F3;
                s_n[r][0] = nn0; s_n[r][1] = nn1; s_n[r][2] = nn2; s_n[r][3] = nn3;
                // e-flag: nn(r) == nn(r-1)?
                u64 de = (nn0 ^ p10) | (nn1 ^ p11) | (nn2 ^ p12) | (nn3 ^ p13);
                e2 = e1; e1 = (de == 0ull);
                u64 nz = nn0 | nn1 | nn2 | nn3;
                if (nz) {
                    if (hmin < 0) hmin = r;
                    hmax = r;
                    cm0 |= nn0; cm1 |= nn1; cm2 |= nn2; cm3 |= nn3;
                    nzflag = 1;
                } else {
                    nzflag = 0;
                }
                p20 = p10; p21 = p11; p22 = p12; p23 = p13;
                p10 = nn0; p11 = nn1; p12 = nn2; p13 = nn3;
            }
            int wmin, wmax;
            if (hmin < 0) {   // empty: argmax-of-all-False semantics
                hmin = 0; hmax = HH - 1; wmin = 0; wmax = WW - 1;
            } else {
                if (cm0)      wmin = __ffsll((long long)cm0) - 1;
                else if (cm1) wmin = 64  + __ffsll((long long)cm1) - 1;
                else if (cm2) wmin = 128 + __ffsll((long long)cm2) - 1;
                else          wmin = 192 + __ffsll((long long)cm3) - 1;
                if (cm3)      wmax = 255 - __clzll((long long)cm3);
                else if (cm2) wmax = 191 - __clzll((long long)cm2);
                else if (cm1) wmax = 127 - __clzll((long long)cm1);
                else          wmax = 63  - __clzll((long long)cm0);
            }
            // rect columns [wmin, wmax)  (wmax EXCLUSIVE, matching reference slice)
#pragma unroll
            for (int j = 0; j < 4; j++)
                s_rect[j] = mask_lt(wmax, j) & ~mask_lt(wmin, j);
            s_hmin = hmin; s_hmax = hmax;
        }
        __syncthreads();

        // ---- fused parallel phase: rect + change-detect + next b1/b2 + next s_eq ----
        {
            const int hmin = s_hmin, hmax = s_hmax;
            const u64 rc0 = s_rect[0], rc1 = s_rect[1], rc2 = s_rect[2], rc3 = s_rect[3];
            u64 diff = 0;
            for (int r = tid; r < HH; r += 128) {
                bool in = (r >= hmin) && (r <= hmax);
                u64 g0 = s_n[r][0] | (in ? rc0 : 0ull);
                u64 g1 = s_n[r][1] | (in ? rc1 : 0ull);
                u64 g2 = s_n[r][2] | (in ? rc2 : 0ull);
                u64 g3 = s_n[r][3] | (in ? rc3 : 0ull);
                diff |= (g0 ^ s_mask[r][0]) | (g1 ^ s_mask[r][1])
                      | (g2 ^ s_mask[r][2]) | (g3 ^ s_mask[r][3]);
                s_mask[r][0] = g0; s_mask[r][1] = g1;
                s_mask[r][2] = g2; s_mask[r][3] = g3;
                // reconstruct next row's new mask locally (s_n written before barrier)
                u64 n0, n1, n2, n3;
                if (r < HH - 2) {
                    bool in1 = (r + 1 >= hmin) && (r + 1 <= hmax);
                    n0 = s_n[r + 1][0] | (in1 ? rc0 : 0ull);
                    n1 = s_n[r + 1][1] | (in1 ? rc1 : 0ull);
                    n2 = s_n[r + 1][2] | (in1 ? rc2 : 0ull);
                    n3 = s_n[r + 1][3] | (in1 ? rc3 : 0ull);
                } else if (r == HH - 2) {
                    n0 = ~0ull; n1 = ~0ull; n2 = ~0ull; n3 = W3MASK;   // below(H-2)=gt
                } else {
                    n0 = n1 = n2 = n3 = 0ull;                           // below(H-1)=0
                }
                u64 bl0 = g0 & n0, bl1 = g1 & n1, bl2 = g2 & n2, bl3 = g3 & n3;
                u64 rt0 = ((g0 >> 1) | (g1 << 63)) & g0;
                u64 rt1 = ((g1 >> 1) | (g2 << 63)) & g1;
                u64 rt2 = ((g2 >> 1) | (g3 << 63)) & g2;
                u64 rt3 = ((g3 >> 1) | (1ull << 30)) & g3;
                s_b1[r][0] = bl0 ^ rt0; s_b1[r][1] = bl1 ^ rt1;
                s_b1[r][2] = bl2 ^ rt2; s_b1[r][3] = bl3 ^ rt3;
                s_b2[r][0] = bl0 & rt0; s_b2[r][1] = bl1 & rt1;
                s_b2[r][2] = bl2 & rt2; s_b2[r][3] = bl3 & rt3;
                // next-pass s_eq: g(r-1)==g(r)==g(r+1), valid for r in [1, H-3]
                int eqv = 0;
                if (r >= 1 && r <= HH - 3) {
                    bool inm = (r - 1 >= hmin) && (r - 1 <= hmax);
                    u64 m0 = s_n[r - 1][0] | (inm ? rc0 : 0ull);
                    u64 m1 = s_n[r - 1][1] | (inm ? rc1 : 0ull);
                    u64 m2 = s_n[r - 1][2] | (inm ? rc2 : 0ull);
                    u64 m3 = s_n[r - 1][3] | (inm ? rc3 : 0ull);
                    u64 d = (m0 ^ g0) | (m1 ^ g1) | (m2 ^ g2) | (m3 ^ g3)
                          | (g0 ^ n0) | (g1 ^ n1) | (g2 ^ n2) | (g3 ^ n3);
                    eqv = (d == 0ull);
                }
                s_eq[r] = eqv;
            }
            if (diff) s_changed = 1;   // benign multi-writer race (all write 1)
        }
        __syncthreads();

        // converged: pass(m)==m, all remaining passes are identity
        if (!s_changed) break;
    }

    // ---- unpack to float ----
    for (int r = warp; r < HH; r += 4) {
#pragma unroll
        for (int c = 0; c < 7; c++) {
            int w = c * 32 + lane;
            oi[r * WW + w] = (float)((s_mask[r][w >> 6] >> (w & 63)) & 1ull);
        }
    }
}

extern "C" void kernel_launch(void* const* d_in, const int* in_sizes, int n_in,
                              void* d_out, int out_size) {
    const float* x = (const float*)d_in[0];
    float* out = (float*)d_out;
    int nimg = in_sizes[0] / IMG;   // B*C = 8
    mask_ca_kernel<<<nimg, 128>>>(x, out);
}